// round 12
// baseline (speedup 1.0000x reference)
#include <cuda_runtime.h>
#include <cuda_bf16.h>
#include <cuda_fp16.h>
#include <cstdint>

#define BATCH 512
#define TSEQ  1020
#define MROWS (BATCH * TSEQ)   // 522240

// ---------------- device scratch (no runtime allocation) ----------------
__device__ __align__(256) __half g_ch [66846720]; // conv out (fp16), [b][oc][l] flat
__device__ __align__(256) float g_xg1 [66846720];  // [M][128] gate-permuted
__device__ __align__(256) float g_h1  [16711680];  // [M][32]
__device__ __align__(256) float g_xg2 [33423360];  // [M][64]
__device__ __align__(256) float g_h2  [ 8355840];  // [M][16]
__device__ __align__(256) float g_xg3 [66846720];  // [M][128]
__device__ __align__(256) float g_w1p [16384];
__device__ __align__(256) float g_b1p [128];
__device__ __align__(256) float g_w2p [2048];
__device__ __align__(256) float g_b2p [64];
__device__ __align__(256) float g_w3p [2048];
__device__ __align__(256) float g_b3p [128];
__device__ __align__(256) __half g_wc [81920];    // conv W fp16 [tap][oc][ic]
__device__ __align__(256) __half g_w1h[16384];    // Wih1 perm fp16 [gate][k]

__device__ __forceinline__ float sigf(float x){ return __fdividef(1.0f, 1.0f + __expf(-x)); }
__device__ __forceinline__ float tanha(float x){ return 2.0f*__fdividef(1.0f,1.0f+__expf(-2.0f*x)) - 1.0f; }
__device__ __forceinline__ uint32_t packh(__half a, __half b){
    return (uint32_t)__half_as_ushort(a) | ((uint32_t)__half_as_ushort(b) << 16);
}

// m16n8k16 fp16 MMA, f32 accum (sm_80+, target-portable)
#define MMAF16(c, a, b) \
    asm volatile("mma.sync.aligned.m16n8k16.row.col.f32.f16.f16.f32 " \
                 "{%0,%1,%2,%3},{%4,%5,%6,%7},{%8,%9},{%0,%1,%2,%3};" \
                 : "+f"((c)[0]), "+f"((c)[1]), "+f"((c)[2]), "+f"((c)[3]) \
                 : "r"((a)[0]), "r"((a)[1]), "r"((a)[2]), "r"((a)[3]), \
                   "r"((b)[0]), "r"((b)[1]))

// ---------------- small prep kernels ----------------
__global__ void k_perm(const float* __restrict__ Wih, const float* __restrict__ bih,
                       const float* __restrict__ bhh, float* __restrict__ Wp,
                       float* __restrict__ bp, int H, int K) {
    int idx = blockIdx.x * 256 + threadIdx.x;
    int N = 4 * H;
    if (idx < N * K) {
        int p = idx / K, k = idx % K;
        int j = p & 3, l = p >> 2;
        Wp[idx] = Wih[(j * H + l) * K + k];
    }
    if (idx < N) {
        int j = idx & 3, l = idx >> 2;
        bp[idx] = bih[j * H + l] + bhh[j * H + l];
    }
}
__global__ void k_wconvh(const float* __restrict__ w, __half* __restrict__ wc) {
    int idx = blockIdx.x * 256 + threadIdx.x;
    if (idx >= 81920) return;
    int k = idx / 16384, rem = idx % 16384, oc = rem / 128, ic = rem % 128;
    wc[idx] = __float2half(w[oc * 640 + ic * 5 + k]);
}
__global__ void k_w1half(const float* __restrict__ w, __half* __restrict__ wh) {
    int idx = blockIdx.x * 256 + threadIdx.x;
    if (idx >= 16384) return;
    wh[idx] = __float2half(w[idx]);
}

// ---------------- HMMA conv: C[oc][l] = sum_{tap} W_tap @ X(shift tap) ----------------
// Single fp16 both operands (1 MMA term). xs staged in 2 ic-chunks of 64.
// smem: xs [64][133]f32 @0 (34048); XTh [132][272B] @34048 (35904); W @69952 (34816).
// Total 104768 -> 2 CTAs/SM.
#define CXS   0
#define CXTH  34048
#define CASH  69952
#define CSMEM 104768
__global__ __launch_bounds__(256) void k_convh(const float* __restrict__ x,
        const __half* __restrict__ wc, const float* __restrict__ cb,
        __half* __restrict__ ch) {
    extern __shared__ char sm[];
    float* xs = (float*)(sm + CXS);
    const int t = threadIdx.x, warp = t >> 5, lane = t & 31;
    const int g = lane >> 2, tid4 = lane & 3;
    const int wm = warp >> 2;      // 0..1 : oc group of 64
    const int wn = warp & 3;       // 0..3 : l group of 32
    const int l0 = blockIdx.x * 128, b = blockIdx.y;

    // build XT[l][ic] fp16 (pitch 272B) in two 64-ic chunks
#pragma unroll 1
    for (int ich = 0; ich < 2; ich++) {
        for (int i = t; i < 64 * 132; i += 256) {
            int ic = i / 132, col = i - ic * 132;
            int gc = l0 + col;
            xs[ic * 133 + col] = (gc < 1024)
                ? x[(size_t)b * 131072 + (size_t)(ich * 64 + ic) * 1024 + gc] : 0.f;
        }
        __syncthreads();
        for (int i = t; i < 132 * 32; i += 256) {
            int l = i >> 5, icp = i & 31;
            __half h0 = __float2half(xs[(2 * icp) * 133 + l]);
            __half h1 = __float2half(xs[(2 * icp + 1) * 133 + l]);
            *(uint32_t*)(sm + CXTH + l * 272 + ich * 128 + icp * 4) = packh(h0, h1);
        }
        __syncthreads();
    }

    float c[4][4][4];
#pragma unroll
    for (int mt = 0; mt < 4; mt++)
#pragma unroll
        for (int nt = 0; nt < 4; nt++)
#pragma unroll
            for (int j = 0; j < 4; j++) c[mt][nt][j] = 0.f;

#pragma unroll 1
    for (int tap = 0; tap < 5; tap++) {
        // stage W_tap fp16 [128 oc][128 ic] -> pitch-272 smem
        for (int i = t; i < 2048; i += 256) {
            int row = i >> 4, q = i & 15;
            *(uint4*)(sm + CASH + row * 272 + q * 16) =
                *(const uint4*)(wc + tap * 16384 + row * 128 + q * 8);
        }
        __syncthreads();
#pragma unroll
        for (int kc = 0; kc < 8; kc++) {
            uint32_t a[4][4], bh[4][2];
            const int kb = kc * 32 + tid4 * 4;
#pragma unroll
            for (int mt = 0; mt < 4; mt++) {
                const char* p = sm + CASH + (wm * 64 + mt * 16 + g) * 272 + kb;
                a[mt][0] = *(const uint32_t*)(p);
                a[mt][1] = *(const uint32_t*)(p + 8 * 272);
                a[mt][2] = *(const uint32_t*)(p + 16);
                a[mt][3] = *(const uint32_t*)(p + 8 * 272 + 16);
            }
#pragma unroll
            for (int nt = 0; nt < 4; nt++) {
                const char* p = sm + CXTH + (wn * 32 + nt * 8 + g + tap) * 272 + kb;
                bh[nt][0] = *(const uint32_t*)(p);
                bh[nt][1] = *(const uint32_t*)(p + 16);
            }
#pragma unroll
            for (int mt = 0; mt < 4; mt++)
#pragma unroll
                for (int nt = 0; nt < 4; nt++)
                    MMAF16(c[mt][nt], a[mt], bh[nt]);
        }
        __syncthreads();
    }

    // epilogue: +bias, store fp16 [b][oc][l]
#pragma unroll
    for (int mt = 0; mt < 4; mt++) {
        int oc = wm * 64 + mt * 16 + g;
        float b0 = __ldg(&cb[oc]), b8 = __ldg(&cb[oc + 8]);
        size_t r0 = ((size_t)b * 128 + oc) * 1020;
        size_t r8 = r0 + 8 * 1020;
#pragma unroll
        for (int nt = 0; nt < 4; nt++) {
            int lg = l0 + wn * 32 + nt * 8 + 2 * tid4;
            if (lg < 1020) {
                *(uint32_t*)&ch[r0 + lg] =
                    packh(__float2half(c[mt][nt][0] + b0), __float2half(c[mt][nt][1] + b0));
                *(uint32_t*)&ch[r8 + lg] =
                    packh(__float2half(c[mt][nt][2] + b8), __float2half(c[mt][nt][3] + b8));
            }
        }
    }
}

// ---------------- HMMA GEMM1: xg1[m][gate] = A[m][:]·W1p[gate][:] + b ----------------
// A = conv out fp16; B = W1 fp16. smem: bias 512 @0; AS @512; BS @35328. Tot 70144 -> 3 CTAs/SM.
#define G_BI  0
#define G_AS  512
#define G_BS  35328
#define G_SMEM 70144
__global__ __launch_bounds__(256) void k_g1h(const __half* __restrict__ ah,
        const __half* __restrict__ w1h,
        const float* __restrict__ bp, float* __restrict__ xg) {
    extern __shared__ char sm[];
    float* bs = (float*)(sm + G_BI);
    const int t = threadIdx.x, warp = t >> 5, lane = t & 31;
    const int g = lane >> 2, tid4 = lane & 3;
    const int wm = warp >> 2;
    const int wn = warp & 3;
    const size_t m0 = (size_t)blockIdx.x * 128;

    if (t < 128) bs[t] = bp[t];
    for (int i = t; i < 2048; i += 256) {
        int row = i >> 4, q = i & 15;
        *(uint4*)(sm + G_AS + row * 272 + q * 16) = *(const uint4*)(ah + (m0 + row) * 128 + q * 8);
        *(uint4*)(sm + G_BS + row * 272 + q * 16) = *(const uint4*)(w1h + row * 128 + q * 8);
    }
    __syncthreads();

    float c[4][4][4];
#pragma unroll
    for (int mt = 0; mt < 4; mt++)
#pragma unroll
        for (int nt = 0; nt < 4; nt++)
#pragma unroll
            for (int j = 0; j < 4; j++) c[mt][nt][j] = 0.f;

#pragma unroll
    for (int kc = 0; kc < 8; kc++) {
        uint32_t a[4][4], bf[4][2];
        const int kb = kc * 32 + tid4 * 4;
#pragma unroll
        for (int mt = 0; mt < 4; mt++) {
            const char* p = sm + G_AS + (wm * 64 + mt * 16 + g) * 272 + kb;
            a[mt][0] = *(const uint32_t*)(p);
            a[mt][1] = *(const uint32_t*)(p + 8 * 272);
            a[mt][2] = *(const uint32_t*)(p + 16);
            a[mt][3] = *(const uint32_t*)(p + 8 * 272 + 16);
        }
#pragma unroll
        for (int nt = 0; nt < 4; nt++) {
            const char* p = sm + G_BS + (wn * 32 + nt * 8 + g) * 272 + kb;
            bf[nt][0] = *(const uint32_t*)(p);
            bf[nt][1] = *(const uint32_t*)(p + 16);
        }
#pragma unroll
        for (int mt = 0; mt < 4; mt++)
#pragma unroll
            for (int nt = 0; nt < 4; nt++)
                MMAF16(c[mt][nt], a[mt], bf[nt]);
    }

#pragma unroll
    for (int mt = 0; mt < 4; mt++) {
        size_t m = m0 + wm * 64 + mt * 16 + g;
#pragma unroll
        for (int nt = 0; nt < 4; nt++) {
            int col = wn * 32 + nt * 8 + 2 * tid4;
            float bx = bs[col], by = bs[col + 1];
            float2 o0 = { c[mt][nt][0] + bx, c[mt][nt][1] + by };
            float2 o1 = { c[mt][nt][2] + bx, c[mt][nt][3] + by };
            *(float2*)&xg[m * 128 + col] = o0;
            *(float2*)&xg[(m + 8) * 128 + col] = o1;
        }
    }
}

// ---------------- fp32 GEMM for layers 2/3 ----------------
template <int N, int K>
__global__ __launch_bounds__(256) void k_gemm(const float* __restrict__ A,
                                              const float* __restrict__ Wp,
                                              const float* __restrict__ bp,
                                              float* __restrict__ Xg) {
    constexpr int KC = 16;
    constexpr int CG = N / 4;
    constexpr int RG = 256 / CG;
    constexpr int RPT = 64 / RG;
    __shared__ float As[64][KC];
    __shared__ float Ws[KC][N];
    const int t = threadIdx.x;
    const int cg = t % CG, rg = t / CG;
    const size_t m0 = (size_t)blockIdx.x * 64;
    float acc[RPT][4];
#pragma unroll
    for (int r = 0; r < RPT; r++)
#pragma unroll
        for (int j = 0; j < 4; j++) acc[r][j] = 0.f;
    for (int kc = 0; kc < K; kc += KC) {
        {
            int row = t >> 2, k4 = (t & 3) * 4;
            *(float4*)&As[row][k4] = *(const float4*)&A[(m0 + row) * K + kc + k4];
        }
#pragma unroll
        for (int e = 0; e < N * KC / 256; e++) {
            int idx = t + e * 256;
            int p = idx % N, kk = idx / N;
            Ws[kk][p] = Wp[p * K + kc + kk];
        }
        __syncthreads();
#pragma unroll
        for (int kk = 0; kk < KC; kk++) {
            float4 w4 = *(const float4*)&Ws[kk][cg * 4];
#pragma unroll
            for (int r = 0; r < RPT; r++) {
                float av = As[rg * RPT + r][kk];
                acc[r][0] += av * w4.x; acc[r][1] += av * w4.y;
                acc[r][2] += av * w4.z; acc[r][3] += av * w4.w;
            }
        }
        __syncthreads();
    }
    float4 bv = *(const float4*)&bp[cg * 4];
#pragma unroll
    for (int r = 0; r < RPT; r++) {
        size_t m = m0 + rg * RPT + r;
        float4 o = { acc[r][0] + bv.x, acc[r][1] + bv.y, acc[r][2] + bv.z, acc[r][3] + bv.w };
        *(float4*)&Xg[m * N + cg * 4] = o;
    }
}

// ---------------- LSTM scans (prefetch + split accumulators) ----------------
__global__ __launch_bounds__(32) void k_scan32(const float* __restrict__ xg,
                                               const float* __restrict__ whh,
                                               float* __restrict__ hout,
                                               float* __restrict__ lastout) {
    const int b = blockIdx.x, l = threadIdx.x;
    float wi[32], wf[32], wg[32], wo[32];
#pragma unroll
    for (int k = 0; k < 32; k++) {
        wi[k] = whh[(0 * 32 + l) * 32 + k];
        wf[k] = whh[(1 * 32 + l) * 32 + k];
        wg[k] = whh[(2 * 32 + l) * 32 + k];
        wo[k] = whh[(3 * 32 + l) * 32 + k];
    }
    float h = 0.f, c = 0.f;
    const float4* xgp = (const float4*)(xg + (size_t)b * TSEQ * 128) + l;
    float4 buf[4];
#pragma unroll
    for (int i = 0; i < 4; i++) buf[i] = xgp[(size_t)i * 32];
    for (int ts = 0; ts < TSEQ; ts += 4) {
#pragma unroll
        for (int j = 0; j < 4; j++) {
            float4 a = buf[j];
            int nts = ts + j + 4;
            if (nts < TSEQ) buf[j] = xgp[(size_t)nts * 32];
            float gi[4] = {a.x, 0.f, 0.f, 0.f};
            float gf[4] = {a.y, 0.f, 0.f, 0.f};
            float gg[4] = {a.z, 0.f, 0.f, 0.f};
            float go[4] = {a.w, 0.f, 0.f, 0.f};
#pragma unroll
            for (int q = 0; q < 4; q++)
#pragma unroll
                for (int k = 0; k < 8; k++) {
                    float hk = __shfl_sync(0xffffffffu, h, q * 8 + k);
                    gi[q] += wi[q * 8 + k] * hk;
                    gf[q] += wf[q * 8 + k] * hk;
                    gg[q] += wg[q * 8 + k] * hk;
                    go[q] += wo[q * 8 + k] * hk;
                }
            float gI = (gi[0] + gi[1]) + (gi[2] + gi[3]);
            float gF = (gf[0] + gf[1]) + (gf[2] + gf[3]);
            float gG = (gg[0] + gg[1]) + (gg[2] + gg[3]);
            float gO = (go[0] + go[1]) + (go[2] + go[3]);
            c = sigf(gF) * c + sigf(gI) * tanha(gG);
            h = sigf(gO) * tanha(c);
            if (hout) hout[((size_t)b * TSEQ + ts + j) * 32 + l] = h;
        }
    }
    if (lastout) lastout[b * 32 + l] = h;
}
__global__ __launch_bounds__(32) void k_scan16(const float* __restrict__ xg,
                                               const float* __restrict__ whh,
                                               float* __restrict__ hout) {
    const int lane = threadIdx.x;
    const int u = lane & 15;
    const int b = blockIdx.x * 2 + (lane >> 4);
    float wi[16], wf[16], wg[16], wo[16];
#pragma unroll
    for (int k = 0; k < 16; k++) {
        wi[k] = whh[(0 * 16 + u) * 16 + k];
        wf[k] = whh[(1 * 16 + u) * 16 + k];
        wg[k] = whh[(2 * 16 + u) * 16 + k];
        wo[k] = whh[(3 * 16 + u) * 16 + k];
    }
    float h = 0.f, c = 0.f;
    const float4* xgp = (const float4*)(xg + (size_t)b * TSEQ * 64) + u;
    float4 buf[4];
#pragma unroll
    for (int i = 0; i < 4; i++) buf[i] = xgp[(size_t)i * 16];
    for (int ts = 0; ts < TSEQ; ts += 4) {
#pragma unroll
        for (int j = 0; j < 4; j++) {
            float4 a = buf[j];
            int nts = ts + j + 4;
            if (nts < TSEQ) buf[j] = xgp[(size_t)nts * 16];
            float gi[2] = {a.x, 0.f}, gf[2] = {a.y, 0.f};
            float gg[2] = {a.z, 0.f}, go[2] = {a.w, 0.f};
#pragma unroll
            for (int q = 0; q < 2; q++)
#pragma unroll
                for (int k = 0; k < 8; k++) {
                    float hk = __shfl_sync(0xffffffffu, h, q * 8 + k, 16);
                    gi[q] += wi[q * 8 + k] * hk;
                    gf[q] += wf[q * 8 + k] * hk;
                    gg[q] += wg[q * 8 + k] * hk;
                    go[q] += wo[q * 8 + k] * hk;
                }
            c = sigf(gf[0] + gf[1]) * c + sigf(gi[0] + gi[1]) * tanha(gg[0] + gg[1]);
            h = sigf(go[0] + go[1]) * tanha(c);
            hout[((size_t)b * TSEQ + ts + j) * 16 + u] = h;
        }
    }
}

// ---------------- launch ----------------
extern "C" void kernel_launch(void* const* d_in, const int* in_sizes, int n_in,
                              void* d_out, int out_size) {
    const float* x      = (const float*)d_in[0];
    const float* conv_w = (const float*)d_in[1];
    const float* conv_b = (const float*)d_in[2];
    const float* Wih1   = (const float*)d_in[3];
    const float* Whh1   = (const float*)d_in[4];
    const float* bih1   = (const float*)d_in[5];
    const float* bhh1   = (const float*)d_in[6];
    const float* Wih2   = (const float*)d_in[7];
    const float* Whh2   = (const float*)d_in[8];
    const float* bih2   = (const float*)d_in[9];
    const float* bhh2   = (const float*)d_in[10];
    const float* Wih3   = (const float*)d_in[11];
    const float* Whh3   = (const float*)d_in[12];
    const float* bih3   = (const float*)d_in[13];
    const float* bhh3   = (const float*)d_in[14];
    float* out = (float*)d_out;

    __half *p_ch, *p_wc, *p_w1h;
    float *p_xg1, *p_h1, *p_xg2, *p_h2, *p_xg3;
    float *p_w1p, *p_b1p, *p_w2p, *p_b2p, *p_w3p, *p_b3p;
    cudaGetSymbolAddress((void**)&p_ch,  g_ch);
    cudaGetSymbolAddress((void**)&p_wc,  g_wc);
    cudaGetSymbolAddress((void**)&p_w1h, g_w1h);
    cudaGetSymbolAddress((void**)&p_xg1, g_xg1);
    cudaGetSymbolAddress((void**)&p_h1,  g_h1);
    cudaGetSymbolAddress((void**)&p_xg2, g_xg2);
    cudaGetSymbolAddress((void**)&p_h2,  g_h2);
    cudaGetSymbolAddress((void**)&p_xg3, g_xg3);
    cudaGetSymbolAddress((void**)&p_w1p, g_w1p);
    cudaGetSymbolAddress((void**)&p_b1p, g_b1p);
    cudaGetSymbolAddress((void**)&p_w2p, g_w2p);
    cudaGetSymbolAddress((void**)&p_b2p, g_b2p);
    cudaGetSymbolAddress((void**)&p_w3p, g_w3p);
    cudaGetSymbolAddress((void**)&p_b3p, g_b3p);

    cudaFuncSetAttribute(k_convh, cudaFuncAttributeMaxDynamicSharedMemorySize, CSMEM);
    cudaFuncSetAttribute(k_g1h,   cudaFuncAttributeMaxDynamicSharedMemorySize, G_SMEM);

    // launch order keeps k_convh as the 4th launch (ncu profiles it)
    k_wconvh<<<320, 256>>>(conv_w, p_wc);                                  // 1
    k_perm<<<64, 256>>>(Wih1, bih1, bhh1, p_w1p, p_b1p, 32, 128);          // 2
    k_w1half<<<64, 256>>>(p_w1p, p_w1h);                                   // 3
    {
        dim3 g(8, BATCH);
        k_convh<<<g, 256, CSMEM>>>(x, p_wc, conv_b, p_ch);                 // 4 <- profiled
    }
    k_perm<<<8,  256>>>(Wih2, bih2, bhh2, p_w2p, p_b2p, 16, 32);           // 5
    k_perm<<<8,  256>>>(Wih3, bih3, bhh3, p_w3p, p_b3p, 32, 16);           // 6
    // layer 1: xg1 (HMMA fp16) ; scan H=32
    k_g1h<<<MROWS / 128, 256, G_SMEM>>>(p_ch, p_w1h, p_b1p, p_xg1);
    k_scan32<<<BATCH, 32>>>(p_xg1, Whh1, p_h1, nullptr);
    // layer 2
    k_gemm<64, 32><<<MROWS / 64, 256>>>(p_h1, p_w2p, p_b2p, p_xg2);
    k_scan16<<<BATCH / 2, 32>>>(p_xg2, Whh2, p_h2);
    // layer 3
    k_gemm<128, 16><<<MROWS / 64, 256>>>(p_h2, p_w3p, p_b3p, p_xg3);
    k_scan32<<<BATCH, 32>>>(p_xg3, Whh3, nullptr, out);
}

// round 13
// speedup vs baseline: 1.4751x; 1.4751x over previous
#include <cuda_runtime.h>
#include <cuda_fp16.h>
#include <cstdint>

#define BATCH 512
#define TSEQ  1020
#define MROWS (BATCH * TSEQ)   // 522240

// ---------------- device scratch ----------------
__device__ __align__(256) __half g_ch [66846720]; // conv out fp16 [b][oc][l]
__device__ __align__(256) __half g_xg1[66846720]; // [M][128] fp16 gate-permuted
__device__ __align__(256) float  g_h1 [16711680]; // [M][32]
__device__ __align__(256) __half g_xg2[33423360]; // [M][64] fp16
__device__ __align__(256) float  g_h2 [ 8355840]; // [M][16]
__device__ __align__(256) __half g_xg3[66846720]; // [M][128] fp16
__device__ __align__(256) float  g_w1p[16384];
__device__ __align__(256) float  g_b1p[128];
__device__ __align__(256) float  g_w2p[2048];
__device__ __align__(256) float  g_b2p[64];
__device__ __align__(256) float  g_w3p[2048];
__device__ __align__(256) float  g_b3p[128];
__device__ __align__(256) __half g_wc [81920];    // conv W fp16 [tap][oc][ic]
__device__ __align__(256) __half g_w1h[16384];    // Wih1 perm fp16

__device__ __forceinline__ float sigf(float x){ return __fdividef(1.0f, 1.0f + __expf(-x)); }
__device__ __forceinline__ float tanha(float x){ return 2.0f*__fdividef(1.0f,1.0f+__expf(-2.0f*x)) - 1.0f; }
__device__ __forceinline__ uint32_t packh(float a, float b){
    __half2 t = __floats2half2_rn(a, b);
    return *(uint32_t*)&t;
}
__device__ __forceinline__ uint32_t s2u(const void* p){
    uint32_t a; asm("{.reg .u64 t; cvta.to.shared.u64 t,%1; cvt.u32.u64 %0,t;}" : "=r"(a) : "l"(p)); return a;
}

#define MMAF16(c, a, b0, b1) \
    asm volatile("mma.sync.aligned.m16n8k16.row.col.f32.f16.f16.f32 " \
                 "{%0,%1,%2,%3},{%4,%5,%6,%7},{%8,%9},{%0,%1,%2,%3};" \
                 : "+f"((c)[0]), "+f"((c)[1]), "+f"((c)[2]), "+f"((c)[3]) \
                 : "r"((a)[0]), "r"((a)[1]), "r"((a)[2]), "r"((a)[3]), \
                   "r"(b0), "r"(b1))
#define LDSM4(r, addr) \
    asm volatile("ldmatrix.sync.aligned.m8n8.x4.shared.b16 {%0,%1,%2,%3},[%4];" \
                 : "=r"((r)[0]), "=r"((r)[1]), "=r"((r)[2]), "=r"((r)[3]) : "r"(addr))
#define CPA(dst, src)  asm volatile("cp.async.ca.shared.global [%0],[%1],16;" :: "r"(dst), "l"(src))
#define CPCOMMIT()     asm volatile("cp.async.commit_group;" ::: "memory")
#define CPWAIT0()      asm volatile("cp.async.wait_group 0;" ::: "memory")

// ---------------- prep ----------------
__global__ void k_perm(const float* __restrict__ Wih, const float* __restrict__ bih,
                       const float* __restrict__ bhh, float* __restrict__ Wp,
                       float* __restrict__ bp, int H, int K) {
    int idx = blockIdx.x * 256 + threadIdx.x;
    int N = 4 * H;
    if (idx < N * K) {
        int p = idx / K, k = idx % K;
        int j = p & 3, l = p >> 2;
        Wp[idx] = Wih[(j * H + l) * K + k];
    }
    if (idx < N) {
        int j = idx & 3, l = idx >> 2;
        bp[idx] = bih[j * H + l] + bhh[j * H + l];
    }
}
__global__ void k_wconvh(const float* __restrict__ w, __half* __restrict__ wc) {
    int idx = blockIdx.x * 256 + threadIdx.x;
    if (idx >= 81920) return;
    int k = idx / 16384, rem = idx % 16384, oc = rem / 128, ic = rem % 128;
    wc[idx] = __float2half(w[oc * 640 + ic * 5 + k]);
}
__global__ void k_w1half(const float* __restrict__ w, __half* __restrict__ wh) {
    int idx = blockIdx.x * 256 + threadIdx.x;
    if (idx >= 16384) return;
    wh[idx] = __float2half(w[idx]);
}

// ---------------- HMMA conv (ldmatrix + cp.async double-buffered W) ----------------
// smem: XT[132][272B] @0 (35904); WB0 @35904; WB1 @70720 (34816 each). xs overlays WB0/1.
#define CWB0  35904
#define CWB1  70720
#define CSMEM 105536
__global__ __launch_bounds__(256) void k_convh(const float* __restrict__ x,
        const __half* __restrict__ wc, const float* __restrict__ cb,
        __half* __restrict__ ch) {
    extern __shared__ char sm[];
    const uint32_t sb = s2u(sm);
    float* xs = (float*)(sm + CWB0);
    const int t = threadIdx.x, warp = t >> 5, lane = t & 31;
    const int g = lane >> 2, tid4 = lane & 3;
    const int wm = warp >> 2, wn = warp & 3;
    const int l0 = blockIdx.x * 128, b = blockIdx.y;

    // build XT[l][ic] fp16 (pitch 272B) in two 64-ic chunks (xs overlays W buffers)
#pragma unroll 1
    for (int ich = 0; ich < 2; ich++) {
        for (int i = t; i < 64 * 132; i += 256) {
            int ic = i / 132, col = i - ic * 132;
            int gc = l0 + col;
            xs[ic * 133 + col] = (gc < 1024)
                ? x[(size_t)b * 131072 + (size_t)(ich * 64 + ic) * 1024 + gc] : 0.f;
        }
        __syncthreads();
        for (int i = t; i < 132 * 32; i += 256) {
            int l = i >> 5, icp = i & 31;
            *(uint32_t*)(sm + l * 272 + ich * 128 + icp * 4) =
                packh(xs[(2 * icp) * 133 + l], xs[(2 * icp + 1) * 133 + l]);
        }
        __syncthreads();
    }

    // stage W tap0 into WB0
    {
        int row = t >> 4, q = t & 15;   // 16 rows per pass
        for (int r8 = 0; r8 < 128; r8 += 16)
            CPA(sb + CWB0 + (row + r8) * 272 + q * 16, wc + (size_t)(row + r8) * 128 + q * 8);
        CPCOMMIT(); CPWAIT0();
    }
    __syncthreads();

    float c[4][4][4];
#pragma unroll
    for (int mt = 0; mt < 4; mt++)
#pragma unroll
        for (int nt = 0; nt < 4; nt++)
#pragma unroll
            for (int j = 0; j < 4; j++) c[mt][nt][j] = 0.f;

    const uint32_t aBaseCom = ((wm * 64 + (lane & 15)) * 272) + (lane >> 4) * 16;
    const uint32_t bBaseCom = sb + ((wn * 32 + ((lane >> 4) & 1) * 8 + (lane & 7)) * 272)
                              + ((lane >> 3) & 1) * 16;

#pragma unroll 1
    for (int tap = 0; tap < 5; tap++) {
        const uint32_t wb = (tap & 1) ? CWB1 : CWB0;
        if (tap < 4) {   // prefetch next tap into other buffer
            const uint32_t wbn = (tap & 1) ? CWB0 : CWB1;
            int row = t >> 4, q = t & 15;
            const __half* src = wc + (size_t)(tap + 1) * 16384;
            for (int r8 = 0; r8 < 128; r8 += 16)
                CPA(sb + wbn + (row + r8) * 272 + q * 16, src + (size_t)(row + r8) * 128 + q * 8);
            CPCOMMIT();
        }
        const uint32_t aBase = sb + wb + aBaseCom;
        const uint32_t bBase = bBaseCom + tap * 272;
#pragma unroll
        for (int kc = 0; kc < 8; kc++) {
            uint32_t a[4][4], bq[4], br[4];
            LDSM4(a[0], aBase + kc * 32);
            LDSM4(a[1], aBase + 4352 + kc * 32);
            LDSM4(a[2], aBase + 2 * 4352 + kc * 32);
            LDSM4(a[3], aBase + 3 * 4352 + kc * 32);
            LDSM4(bq, bBase + kc * 32);
            LDSM4(br, bBase + 4352 + kc * 32);
#pragma unroll
            for (int mt = 0; mt < 4; mt++) {
                MMAF16(c[mt][0], a[mt], bq[0], bq[1]);
                MMAF16(c[mt][1], a[mt], bq[2], bq[3]);
                MMAF16(c[mt][2], a[mt], br[0], br[1]);
                MMAF16(c[mt][3], a[mt], br[2], br[3]);
            }
        }
        CPWAIT0();
        __syncthreads();
    }

    // epilogue: +bias, store fp16 [b][oc][l]
#pragma unroll
    for (int mt = 0; mt < 4; mt++) {
        int oc = wm * 64 + mt * 16 + g;
        float b0 = __ldg(&cb[oc]), b8 = __ldg(&cb[oc + 8]);
        size_t r0 = ((size_t)b * 128 + oc) * 1020;
        size_t r8 = r0 + 8 * 1020;
#pragma unroll
        for (int nt = 0; nt < 4; nt++) {
            int lg = l0 + wn * 32 + nt * 8 + 2 * tid4;
            if (lg < 1020) {
                *(uint32_t*)&ch[r0 + lg] = packh(c[mt][nt][0] + b0, c[mt][nt][1] + b0);
                *(uint32_t*)&ch[r8 + lg] = packh(c[mt][nt][2] + b8, c[mt][nt][3] + b8);
            }
        }
    }
}

// ---------------- HMMA GEMM1 (ldmatrix), fp16 out ----------------
#define G_AS  512
#define G_BS  35328
#define G_SMEM 70144
__global__ __launch_bounds__(256) void k_g1h(const __half* __restrict__ ah,
        const __half* __restrict__ w1h,
        const float* __restrict__ bp, __half* __restrict__ xg) {
    extern __shared__ char sm[];
    const uint32_t sb = s2u(sm);
    float* bs = (float*)sm;
    const int t = threadIdx.x, warp = t >> 5, lane = t & 31;
    const int g = lane >> 2, tid4 = lane & 3;
    const int wm = warp >> 2, wn = warp & 3;
    const size_t m0 = (size_t)blockIdx.x * 128;

    if (t < 128) bs[t] = bp[t];
    for (int i = t; i < 2048; i += 256) {
        int row = i >> 4, q = i & 15;
        *(uint4*)(sm + G_AS + row * 272 + q * 16) = *(const uint4*)(ah + (m0 + row) * 128 + q * 8);
        *(uint4*)(sm + G_BS + row * 272 + q * 16) = *(const uint4*)(w1h + row * 128 + q * 8);
    }
    __syncthreads();

    float c[4][4][4];
#pragma unroll
    for (int mt = 0; mt < 4; mt++)
#pragma unroll
        for (int nt = 0; nt < 4; nt++)
#pragma unroll
            for (int j = 0; j < 4; j++) c[mt][nt][j] = 0.f;

    const uint32_t aBase = sb + G_AS + ((wm * 64 + (lane & 15)) * 272) + (lane >> 4) * 16;
    const uint32_t bBase = sb + G_BS + ((wn * 32 + ((lane >> 4) & 1) * 8 + (lane & 7)) * 272)
                           + ((lane >> 3) & 1) * 16;
#pragma unroll
    for (int kc = 0; kc < 8; kc++) {
        uint32_t a[4][4], bq[4], br[4];
        LDSM4(a[0], aBase + kc * 32);
        LDSM4(a[1], aBase + 4352 + kc * 32);
        LDSM4(a[2], aBase + 2 * 4352 + kc * 32);
        LDSM4(a[3], aBase + 3 * 4352 + kc * 32);
        LDSM4(bq, bBase + kc * 32);
        LDSM4(br, bBase + 4352 + kc * 32);
#pragma unroll
        for (int mt = 0; mt < 4; mt++) {
            MMAF16(c[mt][0], a[mt], bq[0], bq[1]);
            MMAF16(c[mt][1], a[mt], bq[2], bq[3]);
            MMAF16(c[mt][2], a[mt], br[0], br[1]);
            MMAF16(c[mt][3], a[mt], br[2], br[3]);
        }
    }

#pragma unroll
    for (int mt = 0; mt < 4; mt++) {
        size_t m = m0 + wm * 64 + mt * 16 + g;
#pragma unroll
        for (int nt = 0; nt < 4; nt++) {
            int col = wn * 32 + nt * 8 + 2 * tid4;
            float bx = bs[col], by = bs[col + 1];
            *(uint32_t*)&xg[m * 128 + col] = packh(c[mt][nt][0] + bx, c[mt][nt][1] + by);
            *(uint32_t*)&xg[(m + 8) * 128 + col] = packh(c[mt][nt][2] + bx, c[mt][nt][3] + by);
        }
    }
}

// ---------------- fp32 GEMM for layers 2/3, fp16 out ----------------
template <int N, int K>
__global__ __launch_bounds__(256) void k_gemm(const float* __restrict__ A,
                                              const float* __restrict__ Wp,
                                              const float* __restrict__ bp,
                                              __half* __restrict__ Xg) {
    constexpr int KC = 16;
    constexpr int CG = N / 4;
    constexpr int RG = 256 / CG;
    constexpr int RPT = 64 / RG;
    __shared__ float As[64][KC];
    __shared__ float Ws[KC][N];
    const int t = threadIdx.x;
    const int cg = t % CG, rg = t / CG;
    const size_t m0 = (size_t)blockIdx.x * 64;
    float acc[RPT][4];
#pragma unroll
    for (int r = 0; r < RPT; r++)
#pragma unroll
        for (int j = 0; j < 4; j++) acc[r][j] = 0.f;
    for (int kc = 0; kc < K; kc += KC) {
        {
            int row = t >> 2, k4 = (t & 3) * 4;
            *(float4*)&As[row][k4] = *(const float4*)&A[(m0 + row) * K + kc + k4];
        }
#pragma unroll
        for (int e = 0; e < N * KC / 256; e++) {
            int idx = t + e * 256;
            int p = idx % N, kk = idx / N;
            Ws[kk][p] = Wp[p * K + kc + kk];
        }
        __syncthreads();
#pragma unroll
        for (int kk = 0; kk < KC; kk++) {
            float4 w4 = *(const float4*)&Ws[kk][cg * 4];
#pragma unroll
            for (int r = 0; r < RPT; r++) {
                float av = As[rg * RPT + r][kk];
                acc[r][0] += av * w4.x; acc[r][1] += av * w4.y;
                acc[r][2] += av * w4.z; acc[r][3] += av * w4.w;
            }
        }
        __syncthreads();
    }
    float4 bv = *(const float4*)&bp[cg * 4];
#pragma unroll
    for (int r = 0; r < RPT; r++) {
        size_t m = m0 + rg * RPT + r;
        uint32_t* o = (uint32_t*)&Xg[m * N + cg * 4];
        o[0] = packh(acc[r][0] + bv.x, acc[r][1] + bv.y);
        o[1] = packh(acc[r][2] + bv.z, acc[r][3] + bv.w);
    }
}

// ---------------- LSTM scans (HFMA2 + fp16 xg + prefetch) ----------------
__global__ __launch_bounds__(32) void k_scan32(const __half* __restrict__ xg,
                                               const float* __restrict__ whh,
                                               float* __restrict__ hout,
                                               float* __restrict__ lastout) {
    const int b = blockIdx.x, l = threadIdx.x;
    __half2 wif[32], wgo[32];
#pragma unroll
    for (int k = 0; k < 32; k++) {
        wif[k] = __floats2half2_rn(whh[(0 * 32 + l) * 32 + k], whh[(1 * 32 + l) * 32 + k]);
        wgo[k] = __floats2half2_rn(whh[(2 * 32 + l) * 32 + k], whh[(3 * 32 + l) * 32 + k]);
    }
    float h = 0.f, c = 0.f;
    const uint2* xgp = (const uint2*)(xg + (size_t)b * TSEQ * 128) + l;
    uint2 buf[4];
#pragma unroll
    for (int i = 0; i < 4; i++) buf[i] = xgp[(size_t)i * 32];
    for (int ts = 0; ts < TSEQ; ts += 4) {
#pragma unroll
        for (int j = 0; j < 4; j++) {
            uint2 v = buf[j];
            int nts = ts + j + 4;
            if (nts < TSEQ) buf[j] = xgp[(size_t)nts * 32];
            float2 x0 = __half22float2(*(__half2*)&v.x);   // (i,f)
            float2 x1 = __half22float2(*(__half2*)&v.y);   // (g,o)
            __half2 hp = __float2half2_rn(h);
            uint32_t hu = *(uint32_t*)&hp;
            __half2 aA0 = __floats2half2_rn(0.f, 0.f), aB0 = aA0, aA1 = aA0, aB1 = aA0;
#pragma unroll
            for (int k = 0; k < 32; k += 2) {
                uint32_t r0 = __shfl_sync(0xffffffffu, hu, k);
                __half2 h0 = *(__half2*)&r0;
                aA0 = __hfma2(wif[k], h0, aA0);
                aA1 = __hfma2(wgo[k], h0, aA1);
                uint32_t r1 = __shfl_sync(0xffffffffu, hu, k + 1);
                __half2 h1 = *(__half2*)&r1;
                aB0 = __hfma2(wif[k + 1], h1, aB0);
                aB1 = __hfma2(wgo[k + 1], h1, aB1);
            }
            float gI = x0.x + __low2float(aA0) + __low2float(aB0);
            float gF = x0.y + __high2float(aA0) + __high2float(aB0);
            float gG = x1.x + __low2float(aA1) + __low2float(aB1);
            float gO = x1.y + __high2float(aA1) + __high2float(aB1);
            c = sigf(gF) * c + sigf(gI) * tanha(gG);
            h = sigf(gO) * tanha(c);
            if (hout) hout[((size_t)b * TSEQ + ts + j) * 32 + l] = h;
        }
    }
    if (lastout) lastout[b * 32 + l] = h;
}
__global__ __launch_bounds__(32) void k_scan16(const __half* __restrict__ xg,
                                               const float* __restrict__ whh,
                                               float* __restrict__ hout) {
    const int lane = threadIdx.x;
    const int u = lane & 15;
    const int b = blockIdx.x * 2 + (lane >> 4);
    __half2 wif[16], wgo[16];
#pragma unroll
    for (int k = 0; k < 16; k++) {
        wif[k] = __floats2half2_rn(whh[(0 * 16 + u) * 16 + k], whh[(1 * 16 + u) * 16 + k]);
        wgo[k] = __floats2half2_rn(whh[(2 * 16 + u) * 16 + k], whh[(3 * 16 + u) * 16 + k]);
    }
    float h = 0.f, c = 0.f;
    const uint2* xgp = (const uint2*)(xg + (size_t)b * TSEQ * 64) + u;
    uint2 buf[4];
#pragma unroll
    for (int i = 0; i < 4; i++) buf[i] = xgp[(size_t)i * 16];
    for (int ts = 0; ts < TSEQ; ts += 4) {
#pragma unroll
        for (int j = 0; j < 4; j++) {
            uint2 v = buf[j];
            int nts = ts + j + 4;
            if (nts < TSEQ) buf[j] = xgp[(size_t)nts * 16];
            float2 x0 = __half22float2(*(__half2*)&v.x);
            float2 x1 = __half22float2(*(__half2*)&v.y);
            __half2 hp = __float2half2_rn(h);
            uint32_t hu = *(uint32_t*)&hp;
            __half2 aA0 = __floats2half2_rn(0.f, 0.f), aB0 = aA0, aA1 = aA0, aB1 = aA0;
#pragma unroll
            for (int k = 0; k < 16; k += 2) {
                uint32_t r0 = __shfl_sync(0xffffffffu, hu, k, 16);
                __half2 h0 = *(__half2*)&r0;
                aA0 = __hfma2(wif[k], h0, aA0);
                aA1 = __hfma2(wgo[k], h0, aA1);
                uint32_t r1 = __shfl_sync(0xffffffffu, hu, k + 1, 16);
                __half2 h1 = *(__half2*)&r1;
                aB0 = __hfma2(wif[k + 1], h1, aB0);
                aB1 = __hfma2(wgo[k + 1], h1, aB1);
            }
            float gI = x0.x + __low2float(aA0) + __low2float(aB0);
            float gF = x0.y + __high2float(aA0) + __high2float(aB0);
            float gG = x1.x + __low2float(aA1) + __low2float(aB1);
            float gO = x1.y + __high2float(aA1) + __high2float(aB1);
            c = sigf(gF) * c + sigf(gI) * tanha(gG);
            h = sigf(gO) * tanha(c);
            hout[((size_t)b * TSEQ + ts + j) * 16 + u] = h;
        }
    }
}

// ---------------- launch ----------------
extern "C" void kernel_launch(void* const* d_in, const int* in_sizes, int n_in,
                              void* d_out, int out_size) {
    const float* x      = (const float*)d_in[0];
    const float* conv_w = (const float*)d_in[1];
    const float* conv_b = (const float*)d_in[2];
    const float* Wih1   = (const float*)d_in[3];
    const float* Whh1   = (const float*)d_in[4];
    const float* bih1   = (const float*)d_in[5];
    const float* bhh1   = (const float*)d_in[6];
    const float* Wih2   = (const float*)d_in[7];
    const float* Whh2   = (const float*)d_in[8];
    const float* bih2   = (const float*)d_in[9];
    const float* bhh2   = (const float*)d_in[10];
    const float* Wih3   = (const float*)d_in[11];
    const float* Whh3   = (const float*)d_in[12];
    const float* bih3   = (const float*)d_in[13];
    const float* bhh3   = (const float*)d_in[14];
    float* out = (float*)d_out;

    __half *p_ch, *p_wc, *p_w1h, *p_xg1, *p_xg2, *p_xg3;
    float *p_h1, *p_h2;
    float *p_w1p, *p_b1p, *p_w2p, *p_b2p, *p_w3p, *p_b3p;
    cudaGetSymbolAddress((void**)&p_ch,  g_ch);
    cudaGetSymbolAddress((void**)&p_wc,  g_wc);
    cudaGetSymbolAddress((void**)&p_w1h, g_w1h);
    cudaGetSymbolAddress((void**)&p_xg1, g_xg1);
    cudaGetSymbolAddress((void**)&p_h1,  g_h1);
    cudaGetSymbolAddress((void**)&p_xg2, g_xg2);
    cudaGetSymbolAddress((void**)&p_h2,  g_h2);
    cudaGetSymbolAddress((void**)&p_xg3, g_xg3);
    cudaGetSymbolAddress((void**)&p_w1p, g_w1p);
    cudaGetSymbolAddress((void**)&p_b1p, g_b1p);
    cudaGetSymbolAddress((void**)&p_w2p, g_w2p);
    cudaGetSymbolAddress((void**)&p_b2p, g_b2p);
    cudaGetSymbolAddress((void**)&p_w3p, g_w3p);
    cudaGetSymbolAddress((void**)&p_b3p, g_b3p);

    cudaFuncSetAttribute(k_convh, cudaFuncAttributeMaxDynamicSharedMemorySize, CSMEM);
    cudaFuncSetAttribute(k_g1h,   cudaFuncAttributeMaxDynamicSharedMemorySize, G_SMEM);

    // launch order keeps k_convh as the 4th launch (ncu profiles it)
    k_wconvh<<<320, 256>>>(conv_w, p_wc);                                  // 1
    k_perm<<<64, 256>>>(Wih1, bih1, bhh1, p_w1p, p_b1p, 32, 128);          // 2
    k_w1half<<<64, 256>>>(p_w1p, p_w1h);                                   // 3
    {
        dim3 g(8, BATCH);
        k_convh<<<g, 256, CSMEM>>>(x, p_wc, conv_b, p_ch);                 // 4 <- profiled
    }
    k_perm<<<8,  256>>>(Wih2, bih2, bhh2, p_w2p, p_b2p, 16, 32);           // 5
    k_perm<<<8,  256>>>(Wih3, bih3, bhh3, p_w3p, p_b3p, 32, 16);           // 6
    // layer 1
    k_g1h<<<MROWS / 128, 256, G_SMEM>>>(p_ch, p_w1h, p_b1p, p_xg1);
    k_scan32<<<BATCH, 32>>>(p_xg1, Whh1, p_h1, nullptr);
    // layer 2
    k_gemm<64, 32><<<MROWS / 64, 256>>>(p_h1, p_w2p, p_b2p, p_xg2);
    k_scan16<<<BATCH / 2, 32>>>(p_xg2, Whh2, p_h2);
    // layer 3
    k_gemm<128, 16><<<MROWS / 64, 256>>>(p_h2, p_w3p, p_b3p, p_xg3);
    k_scan32<<<BATCH, 32>>>(p_xg3, Whh3, nullptr, out);
}